// round 3
// baseline (speedup 1.0000x reference)
#include <cuda_runtime.h>

namespace {

constexpr int S  = 200;
constexpr int D  = 64;
constexpr int H1 = 64;
constexpr int H2 = 16;
constexpr int THREADS = 256;
constexpr int H1S_STRIDE = 68;          // pad to kill bank conflicts on row reads
constexpr float EPS = 1e-9f;

// ---- dynamic smem layout (float offsets) ----
constexpr int KS_OFF  = 0;                          // S*D      = 12800
constexpr int H1S_OFF = KS_OFF + S * D;             // S*68     = 13600 (aliased: Msm during setup, red in stage3)
constexpr int W2_OFF  = H1S_OFF + S * H1S_STRIDE;   // 64*16    = 1024
constexpr int QS_OFF  = W2_OFF + H1 * H2;           // 64
constexpr int QA_OFF  = QS_OFF + D;                 // 64
constexpr int WT_OFF  = QA_OFF + H1;                // S = 200
constexpr int P2_OFF  = WT_OFF + S;                 // 48 (alpha2, mean2, rstd2)
constexpr int W3_OFF  = P2_OFF + 48;                // 16
constexpr int SMEM_FLOATS = W3_OFF + H2;
constexpr int SMEM_BYTES  = SMEM_FLOATS * 4;        // = 111264 bytes -> 2 CTAs/SM

__device__ __forceinline__ float sigmoidf_fast(float z) {
    return __fdividef(1.0f, 1.0f + __expf(-z));
}

// Dice at inference: x * (alpha + sigmoid((x-mean)*rstd) * (1 - alpha))
__device__ __forceinline__ float dicef(float x, float alpha, float mean, float rstd) {
    float s = sigmoidf_fast((x - mean) * rstd);
    return x * (alpha + s * (1.0f - alpha));
}

__global__ void __launch_bounds__(THREADS, 2)
din_pool_kernel(const float* __restrict__ query, const float* __restrict__ key,
                const int*   __restrict__ seqlen,
                const float* __restrict__ W1, const float* __restrict__ a1,
                const float* __restrict__ m1, const float* __restrict__ v1,
                const float* __restrict__ W2, const float* __restrict__ a2,
                const float* __restrict__ m2, const float* __restrict__ v2,
                const float* __restrict__ W3, float* __restrict__ out)
{
    extern __shared__ float smf[];
    float* ks  = smf + KS_OFF;
    float* h1s = smf + H1S_OFF;
    float* W2s = smf + W2_OFF;
    float* qs  = smf + QS_OFF;
    float* qa  = smf + QA_OFF;
    float* wts = smf + WT_OFF;
    float* P2  = smf + P2_OFF;
    float* W3s = smf + W3_OFF;
    float* Msm = h1s;    // alias: M lives here only until copied to registers
    float* red = h1s;    // alias: stage-3 partials

    const int b = blockIdx.x;
    const int t = threadIdx.x;

    // ---------------- load q, K row, W2, small params ----------------
    if (t < D / 4)
        reinterpret_cast<float4*>(qs)[t] =
            reinterpret_cast<const float4*>(query + (size_t)b * D)[t];

    {
        const float4* kg = reinterpret_cast<const float4*>(key + (size_t)b * S * D);
        float4* ks4 = reinterpret_cast<float4*>(ks);
        #pragma unroll 4
        for (int i = t; i < S * D / 4; i += THREADS) ks4[i] = kg[i];
    }

    reinterpret_cast<float4*>(W2s)[t] = reinterpret_cast<const float4*>(W2)[t]; // 256 float4 exactly

    if (t < H2) {
        P2[t]      = a2[t];
        P2[16 + t] = m2[t];
        P2[32 + t] = rsqrtf(v2[t] + EPS);
        W3s[t]     = W3[t];
    }
    __syncthreads();   // qs visible for M build

    // ---------------- build folded per-batch M (64x64) and qa ----------------
    // att@W1 = q@(W1a+W1c) + k@(W1b - W1c + diag(q)@W1d)
    for (int i = t; i < (D * H1) / 4; i += THREADS) {
        int d = i >> 4, hq = i & 15;
        float4 wb = reinterpret_cast<const float4*>(W1 + (size_t)(D     + d) * H1)[hq];
        float4 wc = reinterpret_cast<const float4*>(W1 + (size_t)(2 * D + d) * H1)[hq];
        float4 wd = reinterpret_cast<const float4*>(W1 + (size_t)(3 * D + d) * H1)[hq];
        float qd = qs[d];
        float4 m;
        m.x = wb.x - wc.x + qd * wd.x;
        m.y = wb.y - wc.y + qd * wd.y;
        m.z = wb.z - wc.z + qd * wd.z;
        m.w = wb.w - wc.w + qd * wd.w;
        reinterpret_cast<float4*>(Msm + d * H1)[hq] = m;
    }
    if (t < H1) {
        float acc = 0.0f;
        #pragma unroll 8
        for (int d = 0; d < D; ++d)
            acc = fmaf(qs[d], W1[(size_t)d * H1 + t] + W1[(size_t)(2 * D + d) * H1 + t], acc);
        qa[t] = acc;
    }
    __syncthreads();

    // ---------------- per-thread column of M into registers ----------------
    const int h      = t & 63;     // output channel owned by this thread
    const int pairId = t >> 6;     // warp pair: position range owner (0..3)
    float Mcol[D];
    #pragma unroll
    for (int d = 0; d < D; ++d) Mcol[d] = Msm[d * H1 + h];
    const float qah = qa[h];
    const float al1 = a1[h], mu1 = m1[h], rs1 = rsqrtf(v1[h] + EPS);
    const int   L   = seqlen[b];
    __syncthreads();   // Msm fully consumed -> h1s region reusable

    // ---------------- stage 1: h1 = dice(K @ M + qa) ----------------
    const int p0 = pairId * (S / 4);
    #pragma unroll 2
    for (int p = p0; p < p0 + S / 4; ++p) {
        const float4* kp = reinterpret_cast<const float4*>(ks + p * D);
        float c0 = 0.f, c1 = 0.f, c2 = 0.f, c3 = 0.f;
        #pragma unroll
        for (int j = 0; j < D / 4; ++j) {
            float4 kv = kp[j];                       // broadcast LDS.128 (warp shares p)
            c0 = fmaf(kv.x, Mcol[4 * j + 0], c0);
            c1 = fmaf(kv.y, Mcol[4 * j + 1], c1);
            c2 = fmaf(kv.z, Mcol[4 * j + 2], c2);
            c3 = fmaf(kv.w, Mcol[4 * j + 3], c3);
        }
        float v = (c0 + c1) + (c2 + c3) + qah;
        h1s[p * H1S_STRIDE + h] = dicef(v, al1, mu1, rs1);
    }
    __syncthreads();

    // ---------------- stage 2: h2 = dice(h1 @ W2), score, weight ----------------
    if (t < S) {
        const float* h1p = h1s + t * H1S_STRIDE;
        float acc[H2];
        #pragma unroll
        for (int j = 0; j < H2; ++j) acc[j] = 0.0f;

        #pragma unroll
        for (int hh = 0; hh < H1; hh += 4) {
            float4 hv = *reinterpret_cast<const float4*>(h1p + hh);  // conflict-free (stride 68)
            float hvals[4] = {hv.x, hv.y, hv.z, hv.w};
            #pragma unroll
            for (int u = 0; u < 4; ++u) {
                const float4* wrow = reinterpret_cast<const float4*>(W2s + (hh + u) * H2);
                float4 w0 = wrow[0], w1 = wrow[1], w2v = wrow[2], w3v = wrow[3]; // broadcast
                float hval = hvals[u];
                acc[0]  = fmaf(hval, w0.x,  acc[0]);
                acc[1]  = fmaf(hval, w0.y,  acc[1]);
                acc[2]  = fmaf(hval, w0.z,  acc[2]);
                acc[3]  = fmaf(hval, w0.w,  acc[3]);
                acc[4]  = fmaf(hval, w1.x,  acc[4]);
                acc[5]  = fmaf(hval, w1.y,  acc[5]);
                acc[6]  = fmaf(hval, w1.z,  acc[6]);
                acc[7]  = fmaf(hval, w1.w,  acc[7]);
                acc[8]  = fmaf(hval, w2v.x, acc[8]);
                acc[9]  = fmaf(hval, w2v.y, acc[9]);
                acc[10] = fmaf(hval, w2v.z, acc[10]);
                acc[11] = fmaf(hval, w2v.w, acc[11]);
                acc[12] = fmaf(hval, w3v.x, acc[12]);
                acc[13] = fmaf(hval, w3v.y, acc[13]);
                acc[14] = fmaf(hval, w3v.z, acc[14]);
                acc[15] = fmaf(hval, w3v.w, acc[15]);
            }
        }
        float score = 0.0f;
        #pragma unroll
        for (int j = 0; j < H2; ++j) {
            float hv2 = dicef(acc[j], P2[j], P2[16 + j], P2[32 + j]);
            score = fmaf(hv2, W3s[j], score);
        }
        // masked score -> sigmoid(NEG_INF) == 0 exactly
        wts[t] = (t < L) ? sigmoidf_fast(score) : 0.0f;
    }
    __syncthreads();

    // ---------------- stage 3: out = sum_p wts[p] * K[p,:] ----------------
    {
        const int d = t & 63, g = t >> 6;
        float acc = 0.0f;
        #pragma unroll 5
        for (int p = g; p < S; p += 4)
            acc = fmaf(wts[p], ks[p * D + d], acc);   // wts broadcast, ks conflict-free
        red[g * D + d] = acc;
    }
    __syncthreads();
    if (t < D) {
        out[(size_t)b * D + t] = (red[t] + red[D + t]) + (red[2 * D + t] + red[3 * D + t]);
    }
}

} // anonymous namespace

extern "C" void kernel_launch(void* const* d_in, const int* in_sizes, int n_in,
                              void* d_out, int out_size)
{
    const float* query = (const float*)d_in[0];
    const float* key   = (const float*)d_in[1];
    const int*   sl    = (const int*)  d_in[2];
    const float* W1    = (const float*)d_in[3];
    const float* a1    = (const float*)d_in[4];
    const float* m1    = (const float*)d_in[5];
    const float* v1    = (const float*)d_in[6];
    const float* W2    = (const float*)d_in[7];
    const float* a2    = (const float*)d_in[8];
    const float* m2    = (const float*)d_in[9];
    const float* v2    = (const float*)d_in[10];
    const float* W3    = (const float*)d_in[11];
    float* out = (float*)d_out;

    const int B = in_sizes[0] / D;   // 2048

    cudaFuncSetAttribute(din_pool_kernel,
                         cudaFuncAttributeMaxDynamicSharedMemorySize, SMEM_BYTES);
    din_pool_kernel<<<B, THREADS, SMEM_BYTES>>>(query, key, sl,
                                                W1, a1, m1, v1,
                                                W2, a2, m2, v2,
                                                W3, out);
}